// round 2
// baseline (speedup 1.0000x reference)
#include <cuda_runtime.h>
#include <math.h>

// Problem constants
#define U 64
#define M 8192
#define D 64

// Output layout (float32, tuple concatenated):
//   outputs  [64,64]        at offset 0           (4096)
//   weights  [64,8192]      at offset 4096        (524288)
//   memories [64,8192,64]   at offset 528384      (33554432)
#define OFF_OUTPUTS  0
#define OFF_WEIGHTS  (U * D)
#define OFF_MEMCOPY  (U * D + U * M)

// Deterministic partial-sum scratch: 64 units * 32 chunks * 64 dims = 512 KB
__device__ float g_partial[U * 32 * D];

// ---------------------------------------------------------------------------
// Kernel 1: scores w[u][m] = dot(attentions[u][m][:], attention[u][:]);
//           w = (mask ? -1e9 : w) / tmpr[u]
// One warp per slot. Each lane loads a float2 -> 32 lanes cover 64 floats,
// 256B fully-coalesced per warp. Raw scores written into the weights region.
// ---------------------------------------------------------------------------
__global__ void k_scores(const float* __restrict__ att,
                         const float* __restrict__ atts,
                         const int*   __restrict__ mask,
                         const float* __restrict__ tmpr,
                         float*       __restrict__ w_out)
{
    int gwarp = (blockIdx.x * blockDim.x + threadIdx.x) >> 5;
    int lane  = threadIdx.x & 31;
    if (gwarp >= U * M) return;
    int u = gwarp >> 13;               // / 8192

    const float2* row = (const float2*)(atts + ((size_t)gwarp << 6));
    const float2* q   = (const float2*)(att  + ((size_t)u << 6));
    float2 a = row[lane];
    float2 b = q[lane];
    float s = a.x * b.x + a.y * b.y;

    #pragma unroll
    for (int o = 16; o > 0; o >>= 1)
        s += __shfl_xor_sync(0xffffffffu, s, o);

    if (lane == 0) {
        if (mask[gwarp]) s = -1e9f;    // RandomMask, applied BEFORE temperature
        w_out[gwarp] = s / tmpr[u];
    }
}

// ---------------------------------------------------------------------------
// Kernel 2: in-place softmax over M=8192 per unit. One 1024-thread block per
// unit; 8 values per thread held in registers; block max + sum reductions.
// Weights region (2 MB) is L2-resident after kernel 1.
// ---------------------------------------------------------------------------
__global__ void k_softmax(float* __restrict__ w)
{
    __shared__ float red[32];
    int u = blockIdx.x;
    int t = threadIdx.x;
    float* row = w + ((size_t)u << 13);

    float v[8];
    float mx = -3.4e38f;
    #pragma unroll
    for (int i = 0; i < 8; i++) {
        v[i] = row[t + i * 1024];
        mx = fmaxf(mx, v[i]);
    }
    // block max
    #pragma unroll
    for (int o = 16; o > 0; o >>= 1)
        mx = fmaxf(mx, __shfl_xor_sync(0xffffffffu, mx, o));
    if ((t & 31) == 0) red[t >> 5] = mx;
    __syncthreads();
    if (t < 32) {
        float m2 = red[t];
        #pragma unroll
        for (int o = 16; o > 0; o >>= 1)
            m2 = fmaxf(m2, __shfl_xor_sync(0xffffffffu, m2, o));
        red[t] = m2;
    }
    __syncthreads();
    mx = red[0];

    float sum = 0.f;
    #pragma unroll
    for (int i = 0; i < 8; i++) {
        v[i] = __expf(v[i] - mx);
        sum += v[i];
    }
    // block sum
    #pragma unroll
    for (int o = 16; o > 0; o >>= 1)
        sum += __shfl_xor_sync(0xffffffffu, sum, o);
    __syncthreads();
    if ((t & 31) == 0) red[t >> 5] = sum;
    __syncthreads();
    if (t < 32) {
        float s2 = red[t];
        #pragma unroll
        for (int o = 16; o > 0; o >>= 1)
            s2 += __shfl_xor_sync(0xffffffffu, s2, o);
        red[t] = s2;
    }
    __syncthreads();
    float inv = 1.0f / red[0];

    #pragma unroll
    for (int i = 0; i < 8; i++)
        row[t + i * 1024] = v[i] * inv;
}

// ---------------------------------------------------------------------------
// Kernel 3: fused (memories copy -> output) + (weights @ memories partials).
// Grid: (32 chunks of 256 slots, 64 units). 256 threads = 16 rows x 16
// float4-lanes (covers D=64). memories read once, copy written once.
// Partial per-(u,chunk) 64-vector -> g_partial (deterministic order).
// ---------------------------------------------------------------------------
__global__ void k_weighted(const float* __restrict__ mem,
                           const float* __restrict__ w,
                           float*       __restrict__ mem_copy,
                           float*       __restrict__ partial)
{
    __shared__ float ws[256];
    __shared__ float4 red[16][16];

    int u     = blockIdx.y;
    int chunk = blockIdx.x;
    int m0    = chunk * 256;
    int tid   = threadIdx.x;

    ws[tid] = w[((size_t)u << 13) + m0 + tid];
    __syncthreads();

    int lane = tid & 15;       // float4 lane over D
    int r    = tid >> 4;       // row group (16 rows at a time)

    size_t base = ((size_t)u << 19) + ((size_t)m0 << 6);   // floats
    const float4* src = (const float4*)(mem + base);
    float4*       dst = (float4*)(mem_copy + base);

    float4 acc = make_float4(0.f, 0.f, 0.f, 0.f);
    #pragma unroll
    for (int i = 0; i < 16; i++) {
        int m = r + i * 16;                 // local slot within chunk
        float4 v = src[(size_t)m * 16 + lane];
        dst[(size_t)m * 16 + lane] = v;     // fused copy of memories
        float wm = ws[m];
        acc.x = fmaf(wm, v.x, acc.x);
        acc.y = fmaf(wm, v.y, acc.y);
        acc.z = fmaf(wm, v.z, acc.z);
        acc.w = fmaf(wm, v.w, acc.w);
    }

    red[r][lane] = acc;
    __syncthreads();
    if (r == 0) {
        float4 s = red[0][lane];
        #pragma unroll
        for (int j = 1; j < 16; j++) {
            s.x += red[j][lane].x;
            s.y += red[j][lane].y;
            s.z += red[j][lane].z;
            s.w += red[j][lane].w;
        }
        ((float4*)partial)[((size_t)u * 32 + chunk) * 16 + lane] = s;
    }
}

// ---------------------------------------------------------------------------
// Kernel 4: outputs[u][d] = sum over 32 chunk-partials (deterministic).
// ---------------------------------------------------------------------------
__global__ void k_reduce(const float* __restrict__ partial,
                         float*       __restrict__ outputs)
{
    int u = blockIdx.x;
    int d = threadIdx.x;
    float s = 0.f;
    #pragma unroll
    for (int c = 0; c < 32; c++)
        s += partial[(((size_t)u * 32 + c) << 6) + d];
    outputs[((size_t)u << 6) + d] = s;
}

// ---------------------------------------------------------------------------
extern "C" void kernel_launch(void* const* d_in, const int* in_sizes, int n_in,
                              void* d_out, int out_size)
{
    const float* att  = (const float*)d_in[0];   // [64,64]
    const float* atts = (const float*)d_in[1];   // [64,8192,64]
    const float* mem  = (const float*)d_in[2];   // [64,8192,64]
    const float* tmpr = (const float*)d_in[3];   // [64,1]
    const int*   mask = (const int*)  d_in[4];   // [64,8192] bool->int32

    float* out      = (float*)d_out;
    float* outputs  = out + OFF_OUTPUTS;
    float* weights  = out + OFF_WEIGHTS;
    float* mem_copy = out + OFF_MEMCOPY;

    float* partial;
    cudaGetSymbolAddress((void**)&partial, g_partial);

    // 1) scores -> weights region (raw)
    {
        int warps = U * M;                 // 524288
        int threads = 256;                 // 8 warps/block
        int blocks = (warps * 32 + threads - 1) / threads;   // 65536
        k_scores<<<blocks, threads>>>(att, atts, mask, tmpr, weights);
    }
    // 2) softmax in place
    k_softmax<<<U, 1024>>>(weights);
    // 3) fused memories copy + weighted-sum partials
    {
        dim3 grid(32, U);
        k_weighted<<<grid, 256>>>(mem, weights, mem_copy, partial);
    }
    // 4) final reduce -> outputs
    k_reduce<<<U, D>>>(partial, outputs);
}

// round 3
// speedup vs baseline: 1.2611x; 1.2611x over previous
#include <cuda_runtime.h>
#include <math.h>

// Problem constants
#define U 64
#define M 8192
#define D 64
#define CHUNKS 16
#define SLOTS_PER_CHUNK (M / CHUNKS)   // 512

// Output layout (float32, tuple concatenated):
//   outputs  [64,64]        at 0
//   weights  [64,8192]      at 4096
//   memories [64,8192,64]   at 528384
#define OFF_OUTPUTS  0
#define OFF_WEIGHTS  (U * D)
#define OFF_MEMCOPY  (U * D + U * M)

// Deterministic partial-sum scratch: 64 units * 16 chunks * 64 dims = 256 KB
__device__ float g_partial[U * CHUNKS * D];

// ---------------------------------------------------------------------------
// Kernel 1: scores. Grid (64 chunks, 64 units), block 256 = 8 warps.
// Each warp handles 16 slots: lanes split into two halves of 16; each half
// covers one 64-float row with float4 loads (LDG.128, 512B per warp step).
// 8 independent iterations -> MLP 8. 4-shuffle reduce over 16 lanes.
// ---------------------------------------------------------------------------
__global__ void k_scores(const float* __restrict__ att,
                         const float* __restrict__ atts,
                         const int*   __restrict__ mask,
                         const float* __restrict__ tmpr,
                         float*       __restrict__ w_out)
{
    int u    = blockIdx.y;
    int warp = threadIdx.x >> 5;          // 0..7
    int lane = threadIdx.x & 31;
    int idx  = lane & 15;                 // float4 lane within row
    int half = lane >> 4;                 // which of 2 rows this step
    int slot0 = blockIdx.x * 128 + warp * 16;

    float4 q4    = ((const float4*)(att + (u << 6)))[idx];
    float  inv_t = 1.0f / tmpr[u];
    const float4* base = (const float4*)(atts + ((size_t)u << 19));
    float*       wrow = w_out + ((size_t)u << 13);
    const int*   mrow = mask  + ((size_t)u << 13);

    #pragma unroll
    for (int i = 0; i < 8; i++) {
        int m = slot0 + 2 * i + half;
        float4 r = __ldcs(&base[(size_t)m * 16 + idx]);
        float s = r.x * q4.x + r.y * q4.y + r.z * q4.z + r.w * q4.w;
        s += __shfl_xor_sync(0xffffffffu, s, 8);
        s += __shfl_xor_sync(0xffffffffu, s, 4);
        s += __shfl_xor_sync(0xffffffffu, s, 2);
        s += __shfl_xor_sync(0xffffffffu, s, 1);
        if (idx == 0) {
            if (mrow[m]) s = -1e9f;        // RandomMask before temperature
            wrow[m] = s * inv_t;
        }
    }
}

// ---------------------------------------------------------------------------
// Kernel 2: in-place softmax over M=8192 per unit. One 1024-thread block per
// unit; 8 values per thread in registers; block max + sum reductions.
// ---------------------------------------------------------------------------
__global__ void k_softmax(float* __restrict__ w)
{
    __shared__ float red[32];
    int u = blockIdx.x;
    int t = threadIdx.x;
    float* row = w + ((size_t)u << 13);

    float v[8];
    float mx = -3.4e38f;
    #pragma unroll
    for (int i = 0; i < 8; i++) {
        v[i] = row[t + i * 1024];
        mx = fmaxf(mx, v[i]);
    }
    #pragma unroll
    for (int o = 16; o > 0; o >>= 1)
        mx = fmaxf(mx, __shfl_xor_sync(0xffffffffu, mx, o));
    if ((t & 31) == 0) red[t >> 5] = mx;
    __syncthreads();
    if (t < 32) {
        float m2 = red[t];
        #pragma unroll
        for (int o = 16; o > 0; o >>= 1)
            m2 = fmaxf(m2, __shfl_xor_sync(0xffffffffu, m2, o));
        red[t] = m2;
    }
    __syncthreads();
    mx = red[0];

    float sum = 0.f;
    #pragma unroll
    for (int i = 0; i < 8; i++) {
        v[i] = __expf(v[i] - mx);
        sum += v[i];
    }
    #pragma unroll
    for (int o = 16; o > 0; o >>= 1)
        sum += __shfl_xor_sync(0xffffffffu, sum, o);
    __syncthreads();
    if ((t & 31) == 0) red[t >> 5] = sum;
    __syncthreads();
    if (t < 32) {
        float s2 = red[t];
        #pragma unroll
        for (int o = 16; o > 0; o >>= 1)
            s2 += __shfl_xor_sync(0xffffffffu, s2, o);
        red[t] = s2;
    }
    __syncthreads();
    float inv = 1.0f / red[0];

    #pragma unroll
    for (int i = 0; i < 8; i++)
        row[t + i * 1024] = v[i] * inv;
}

// ---------------------------------------------------------------------------
// Kernel 3: fused (memories copy) + (weights @ memories partials).
// Grid (16 chunks of 512 slots, 64 units), 256 threads = 16 rows x 16 lanes.
// Streaming loads/stores (.cs) keep the 256MB memories stream out of L2's way.
// ---------------------------------------------------------------------------
__global__ void k_weighted(const float* __restrict__ mem,
                           const float* __restrict__ w,
                           float*       __restrict__ mem_copy,
                           float*       __restrict__ partial)
{
    __shared__ float  ws[SLOTS_PER_CHUNK];
    __shared__ float4 red[16][16];

    int u     = blockIdx.y;
    int chunk = blockIdx.x;
    int m0    = chunk * SLOTS_PER_CHUNK;
    int tid   = threadIdx.x;

    ws[tid]       = w[((size_t)u << 13) + m0 + tid];
    ws[tid + 256] = w[((size_t)u << 13) + m0 + 256 + tid];
    __syncthreads();

    int lane = tid & 15;
    int r    = tid >> 4;

    size_t base = ((size_t)u << 19) + ((size_t)m0 << 6);
    const float4* src = (const float4*)(mem + base);
    float4*       dst = (float4*)(mem_copy + base);

    float4 acc = make_float4(0.f, 0.f, 0.f, 0.f);
    #pragma unroll 8
    for (int i = 0; i < SLOTS_PER_CHUNK / 16; i++) {   // 32 iterations
        int m = r + i * 16;
        float4 v = __ldcs(&src[(size_t)m * 16 + lane]);
        __stcs(&dst[(size_t)m * 16 + lane], v);
        float wm = ws[m];
        acc.x = fmaf(wm, v.x, acc.x);
        acc.y = fmaf(wm, v.y, acc.y);
        acc.z = fmaf(wm, v.z, acc.z);
        acc.w = fmaf(wm, v.w, acc.w);
    }

    red[r][lane] = acc;
    __syncthreads();
    if (r == 0) {
        float4 s = red[0][lane];
        #pragma unroll
        for (int j = 1; j < 16; j++) {
            s.x += red[j][lane].x;
            s.y += red[j][lane].y;
            s.z += red[j][lane].z;
            s.w += red[j][lane].w;
        }
        ((float4*)partial)[((size_t)u * CHUNKS + chunk) * 16 + lane] = s;
    }
}

// ---------------------------------------------------------------------------
// Kernel 4: outputs[u][d] = sum over 16 chunk-partials. float4-vectorized,
// 1024 threads, all data L2-resident.
// ---------------------------------------------------------------------------
__global__ void k_reduce(const float4* __restrict__ partial,
                         float4*       __restrict__ outputs)
{
    int t = blockIdx.x * blockDim.x + threadIdx.x;   // 0..1023
    int u = t >> 4;
    int l = t & 15;
    float4 s = make_float4(0.f, 0.f, 0.f, 0.f);
    #pragma unroll
    for (int c = 0; c < CHUNKS; c++) {
        float4 p = partial[((size_t)(u * CHUNKS + c) << 4) + l];
        s.x += p.x; s.y += p.y; s.z += p.z; s.w += p.w;
    }
    outputs[t] = s;
}

// ---------------------------------------------------------------------------
extern "C" void kernel_launch(void* const* d_in, const int* in_sizes, int n_in,
                              void* d_out, int out_size)
{
    const float* att  = (const float*)d_in[0];   // [64,64]
    const float* atts = (const float*)d_in[1];   // [64,8192,64]
    const float* mem  = (const float*)d_in[2];   // [64,8192,64]
    const float* tmpr = (const float*)d_in[3];   // [64,1]
    const int*   mask = (const int*)  d_in[4];   // [64,8192] bool->int32

    float* out      = (float*)d_out;
    float* outputs  = out + OFF_OUTPUTS;
    float* weights  = out + OFF_WEIGHTS;
    float* mem_copy = out + OFF_MEMCOPY;

    float* partial;
    cudaGetSymbolAddress((void**)&partial, g_partial);

    // 1) scores -> weights region (raw)
    {
        dim3 grid(64, U);          // 64 chunks of 128 slots x 64 units
        k_scores<<<grid, 256>>>(att, atts, mask, tmpr, weights);
    }
    // 2) softmax in place
    k_softmax<<<U, 1024>>>(weights);
    // 3) fused memories copy + weighted-sum partials
    {
        dim3 grid(CHUNKS, U);
        k_weighted<<<grid, 256>>>(mem, weights, mem_copy, partial);
    }
    // 4) final reduce -> outputs
    k_reduce<<<4, 256>>>((const float4*)partial, (float4*)outputs);
}